// round 14
// baseline (speedup 1.0000x reference)
#include <cuda_runtime.h>
#include <cstdint>

// PARCOR -> LPC (Levinson step-up), rows x 25 f32. HBM-bound.
// R5 measured-best config + ONE new variable: L2 evict_first policy on the
// per-warp bulk STORES only (output is write-once/never-read; early steady
// writeback smooths DRAM R/W turnaround). Everything else identical:
// one 25.6 KB CTA-level bulk-async load, register Levinson recurrence,
// 8 independent per-warp 3200 B bulk-async stores. 256 thr, 8 CTAs/SM.

#define ORDER 25
#define RPB   256                       // rows per tile, one thread per row
#define TILE_FLOATS (RPB * ORDER)       // 6400
#define TILE_BYTES  (TILE_FLOATS * 4)   // 25600
#define WARP_FLOATS (32 * ORDER)        // 800
#define WARP_BYTES  (WARP_FLOATS * 4)   // 3200 (16B-multiple)

__device__ __forceinline__ uint32_t smem_u32(const void* p) {
    uint32_t a;
    asm volatile("{ .reg .u64 x; cvta.to.shared.u64 x, %1; cvt.u32.u64 %0, x; }"
                 : "=r"(a) : "l"(p));
    return a;
}

__global__ __launch_bounds__(RPB, 8)
void parcor_to_lpc_bulk(const float* __restrict__ in, float* __restrict__ out)
{
    extern __shared__ __align__(128) float buf[];   // TILE_FLOATS
    __shared__ __align__(8) unsigned long long mbar;

    const int t = threadIdx.x;
    const int w = t >> 5;
    const uint32_t buf_a  = smem_u32(buf);
    const uint32_t mbar_a = smem_u32(&mbar);

    const float* gsrc = in  + (size_t)blockIdx.x * TILE_FLOATS;
    float*       gdst = out + (size_t)blockIdx.x * TILE_FLOATS;

    // ---- one bulk G->S load for the whole tile (single long burst) ----
    if (t == 0) {
        asm volatile("mbarrier.init.shared.b64 [%0], 1;" :: "r"(mbar_a) : "memory");
        asm volatile("fence.proxy.async.shared::cta;" ::: "memory");
        asm volatile("mbarrier.arrive.expect_tx.shared.b64 _, [%0], %1;"
                     :: "r"(mbar_a), "r"((uint32_t)TILE_BYTES) : "memory");
        asm volatile("cp.async.bulk.shared::cta.global.mbarrier::complete_tx::bytes "
                     "[%0], [%1], %2, [%3];"
                     :: "r"(buf_a), "l"(gsrc), "r"((uint32_t)TILE_BYTES), "r"(mbar_a)
                     : "memory");
    }
    __syncthreads();   // mbar init visible to all waiters

    // ---- all threads wait for tile arrival ----
    {
        uint32_t done;
        asm volatile(
            "{\n\t.reg .pred p;\n\t"
            "mbarrier.try_wait.parity.acquire.cta.shared::cta.b64 p, [%1], 0;\n\t"
            "selp.b32 %0, 1, 0, p;\n\t}"
            : "=r"(done) : "r"(mbar_a) : "memory");
        if (!done) {
            asm volatile(
                "{\n\t.reg .pred P1;\n\t"
                "WL_%=:\n\t"
                "mbarrier.try_wait.parity.acquire.cta.shared::cta.b64 P1, [%0], 0, 0x989680;\n\t"
                "@P1 bra.uni WD_%=;\n\t"
                "bra.uni WL_%=;\n\t"
                "WD_%=:\n\t}"
                :: "r"(mbar_a) : "memory");
        }
    }

    // ---- row -> registers (stride-25 words: gcd(25,32)=1, conflict-free) ----
    float a[ORDER];
    float* bp = buf + t * ORDER;
    #pragma unroll
    for (int i = 0; i < ORDER; ++i) a[i] = bp[i];

    // ---- Levinson step-up, fully unrolled; a[m]==k[m] when step m runs
    //      (index m is first modified at step m+1) ----
    #pragma unroll
    for (int m = 2; m < ORDER; ++m) {
        const float km = a[m];
        #pragma unroll
        for (int j = 1; 2 * j < m; ++j) {
            const float tj = a[j];
            const float tk = a[m - j];
            a[j]     = fmaf(km, tk, tj);
            a[m - j] = fmaf(km, tj, tk);
        }
        if ((m & 1) == 0) {
            const int j = m >> 1;
            a[j] = fmaf(km, a[j], a[j]);
        }
    }

    // ---- write back to OWN slots ----
    #pragma unroll
    for (int i = 0; i < ORDER; ++i) bp[i] = a[i];

    // ---- per-warp bulk store with evict_first (write-once stream) ----
    __syncwarp();
    if ((t & 31) == 0) {
        uint64_t pol;
        asm volatile("createpolicy.fractional.L2::evict_first.b64 %0, 1.0;" : "=l"(pol));
        asm volatile("fence.proxy.async.shared::cta;" ::: "memory");
        asm volatile("cp.async.bulk.global.shared::cta.bulk_group"
                     ".L2::cache_hint [%0], [%1], %2, %3;"
                     :: "l"(gdst + w * WARP_FLOATS),
                        "r"(buf_a + (uint32_t)(w * WARP_BYTES)),
                        "r"((uint32_t)WARP_BYTES), "l"(pol) : "memory");
        asm volatile("cp.async.bulk.commit_group;" ::: "memory");
        // smem must be fully read by the bulk engine before CTA exit
        asm volatile("cp.async.bulk.wait_group.read 0;" ::: "memory");
    }
}

// Fallback for row counts not divisible by RPB (not hit by the bench shape).
__global__ void parcor_to_lpc_scalar(const float* __restrict__ in,
                                     float* __restrict__ out, int rows)
{
    int r = blockIdx.x * blockDim.x + threadIdx.x;
    if (r >= rows) return;
    float a[ORDER];
    #pragma unroll
    for (int i = 0; i < ORDER; ++i) a[i] = in[(size_t)r * ORDER + i];
    #pragma unroll
    for (int m = 2; m < ORDER; ++m) {
        const float km = a[m];
        #pragma unroll
        for (int j = 1; 2 * j < m; ++j) {
            const float tj = a[j];
            const float tk = a[m - j];
            a[j]     = fmaf(km, tk, tj);
            a[m - j] = fmaf(km, tj, tk);
        }
        if ((m & 1) == 0) { const int j = m >> 1; a[j] = fmaf(km, a[j], a[j]); }
    }
    #pragma unroll
    for (int i = 0; i < ORDER; ++i) out[(size_t)r * ORDER + i] = a[i];
}

extern "C" void kernel_launch(void* const* d_in, const int* in_sizes, int n_in,
                              void* d_out, int out_size)
{
    const float* k = (const float*)d_in[0];
    float* out = (float*)d_out;

    const int total_elems = in_sizes[0];
    const int rows = total_elems / ORDER;

    if (rows % RPB == 0) {
        cudaFuncSetAttribute(parcor_to_lpc_bulk,
                             cudaFuncAttributeMaxDynamicSharedMemorySize, TILE_BYTES);
        parcor_to_lpc_bulk<<<rows / RPB, RPB, TILE_BYTES>>>(k, out);
    } else {
        parcor_to_lpc_scalar<<<(rows + 255) / 256, 256>>>(k, out, rows);
    }
}

// round 15
// speedup vs baseline: 1.0155x; 1.0155x over previous
#include <cuda_runtime.h>
#include <cstdint>

// PARCOR -> LPC (Levinson step-up), rows x 25 f32. HBM-bound (FINAL).
// Best measured config (R5): one 25.6 KB CTA-level bulk-async load (long
// read burst), register-resident Levinson recurrence, 8 independent per-warp
// 3200 B bulk-async stores (no CTA-level store barrier). 256 thr, 8 CTAs/SM,
// regs=32. Measured 57.9-59.4 us kernel at 6.1-6.25 TB/s (77-79% DRAM) —
// the mixed-R/W HBM floor for this pattern. All variants measured equal or
// worse across rounds 1-14: persistent ring (-35%), 12.8/51.2 KB tiles,
// per-warp loads, evict_first on loads and/or stores.

#define ORDER 25
#define RPB   256                       // rows per tile, one thread per row
#define TILE_FLOATS (RPB * ORDER)       // 6400
#define TILE_BYTES  (TILE_FLOATS * 4)   // 25600
#define WARP_FLOATS (32 * ORDER)        // 800
#define WARP_BYTES  (WARP_FLOATS * 4)   // 3200 (16B-multiple)

__device__ __forceinline__ uint32_t smem_u32(const void* p) {
    uint32_t a;
    asm volatile("{ .reg .u64 x; cvta.to.shared.u64 x, %1; cvt.u32.u64 %0, x; }"
                 : "=r"(a) : "l"(p));
    return a;
}

__global__ __launch_bounds__(RPB, 8)
void parcor_to_lpc_bulk(const float* __restrict__ in, float* __restrict__ out)
{
    extern __shared__ __align__(128) float buf[];   // TILE_FLOATS
    __shared__ __align__(8) unsigned long long mbar;

    const int t = threadIdx.x;
    const int w = t >> 5;
    const uint32_t buf_a  = smem_u32(buf);
    const uint32_t mbar_a = smem_u32(&mbar);

    const float* gsrc = in  + (size_t)blockIdx.x * TILE_FLOATS;
    float*       gdst = out + (size_t)blockIdx.x * TILE_FLOATS;

    // ---- one bulk G->S load for the whole tile (single long burst) ----
    if (t == 0) {
        asm volatile("mbarrier.init.shared.b64 [%0], 1;" :: "r"(mbar_a) : "memory");
        asm volatile("fence.proxy.async.shared::cta;" ::: "memory");
        asm volatile("mbarrier.arrive.expect_tx.shared.b64 _, [%0], %1;"
                     :: "r"(mbar_a), "r"((uint32_t)TILE_BYTES) : "memory");
        asm volatile("cp.async.bulk.shared::cta.global.mbarrier::complete_tx::bytes "
                     "[%0], [%1], %2, [%3];"
                     :: "r"(buf_a), "l"(gsrc), "r"((uint32_t)TILE_BYTES), "r"(mbar_a)
                     : "memory");
    }
    __syncthreads();   // mbar init visible to all waiters

    // ---- all threads wait for tile arrival ----
    {
        uint32_t done;
        asm volatile(
            "{\n\t.reg .pred p;\n\t"
            "mbarrier.try_wait.parity.acquire.cta.shared::cta.b64 p, [%1], 0;\n\t"
            "selp.b32 %0, 1, 0, p;\n\t}"
            : "=r"(done) : "r"(mbar_a) : "memory");
        if (!done) {
            asm volatile(
                "{\n\t.reg .pred P1;\n\t"
                "WL_%=:\n\t"
                "mbarrier.try_wait.parity.acquire.cta.shared::cta.b64 P1, [%0], 0, 0x989680;\n\t"
                "@P1 bra.uni WD_%=;\n\t"
                "bra.uni WL_%=;\n\t"
                "WD_%=:\n\t}"
                :: "r"(mbar_a) : "memory");
        }
    }

    // ---- row -> registers (stride-25 words: gcd(25,32)=1, conflict-free) ----
    float a[ORDER];
    float* bp = buf + t * ORDER;
    #pragma unroll
    for (int i = 0; i < ORDER; ++i) a[i] = bp[i];

    // ---- Levinson step-up, fully unrolled; a[m]==k[m] when step m runs
    //      (index m is first modified at step m+1) ----
    #pragma unroll
    for (int m = 2; m < ORDER; ++m) {
        const float km = a[m];
        #pragma unroll
        for (int j = 1; 2 * j < m; ++j) {
            const float tj = a[j];
            const float tk = a[m - j];
            a[j]     = fmaf(km, tk, tj);
            a[m - j] = fmaf(km, tj, tk);
        }
        if ((m & 1) == 0) {
            const int j = m >> 1;
            a[j] = fmaf(km, a[j], a[j]);
        }
    }

    // ---- write back to OWN slots ----
    #pragma unroll
    for (int i = 0; i < ORDER; ++i) bp[i] = a[i];

    // ---- per-warp bulk store: warp's 3200B region written only by its own
    //      lanes -> __syncwarp suffices; no CTA-level store barrier ----
    __syncwarp();
    if ((t & 31) == 0) {
        asm volatile("fence.proxy.async.shared::cta;" ::: "memory");
        asm volatile("cp.async.bulk.global.shared::cta.bulk_group [%0], [%1], %2;"
                     :: "l"(gdst + w * WARP_FLOATS),
                        "r"(buf_a + (uint32_t)(w * WARP_BYTES)),
                        "r"((uint32_t)WARP_BYTES) : "memory");
        asm volatile("cp.async.bulk.commit_group;" ::: "memory");
        // smem must be fully read by the bulk engine before CTA exit
        asm volatile("cp.async.bulk.wait_group.read 0;" ::: "memory");
    }
}

// Fallback for row counts not divisible by RPB (not hit by the bench shape).
__global__ void parcor_to_lpc_scalar(const float* __restrict__ in,
                                     float* __restrict__ out, int rows)
{
    int r = blockIdx.x * blockDim.x + threadIdx.x;
    if (r >= rows) return;
    float a[ORDER];
    #pragma unroll
    for (int i = 0; i < ORDER; ++i) a[i] = in[(size_t)r * ORDER + i];
    #pragma unroll
    for (int m = 2; m < ORDER; ++m) {
        const float km = a[m];
        #pragma unroll
        for (int j = 1; 2 * j < m; ++j) {
            const float tj = a[j];
            const float tk = a[m - j];
            a[j]     = fmaf(km, tk, tj);
            a[m - j] = fmaf(km, tj, tk);
        }
        if ((m & 1) == 0) { const int j = m >> 1; a[j] = fmaf(km, a[j], a[j]); }
    }
    #pragma unroll
    for (int i = 0; i < ORDER; ++i) out[(size_t)r * ORDER + i] = a[i];
}

extern "C" void kernel_launch(void* const* d_in, const int* in_sizes, int n_in,
                              void* d_out, int out_size)
{
    const float* k = (const float*)d_in[0];
    float* out = (float*)d_out;

    const int total_elems = in_sizes[0];
    const int rows = total_elems / ORDER;

    if (rows % RPB == 0) {
        cudaFuncSetAttribute(parcor_to_lpc_bulk,
                             cudaFuncAttributeMaxDynamicSharedMemorySize, TILE_BYTES);
        parcor_to_lpc_bulk<<<rows / RPB, RPB, TILE_BYTES>>>(k, out);
    } else {
        parcor_to_lpc_scalar<<<(rows + 255) / 256, 256>>>(k, out, rows);
    }
}